// round 10
// baseline (speedup 1.0000x reference)
#include <cuda_runtime.h>
#include <cuda_fp16.h>
#include <cstdint>

#define NSTEPS 32

// ---- smem layout (bytes) ----
#define OFF_W1T 0        // 4 nets x 64 n x 72 halves (pitch 144B) = 36864
#define OFF_A   36864    // 8 warps x 2 nets x 16 rows x 128B (XOR-swizzled) = 32768
#define OFF_W04 69632    // float4[256]
#define OFF_CB  73728    // float[256]  cb = w.z*rf + b0
#define OFF_BW  74752    // float2[256] (b1, w2)
#define OFF_B2  76800    // float[4]
#define OFF_RED 76816    // float[8]
#define SMEM_BYTES 76848

#define A_WARP_B   4096
#define A_NET_B    2048
#define A_PITCH_B  128
#define B_NET_B    9216
#define B_ROW_B    144

__device__ float g_partial[256];

__device__ __forceinline__ uint32_t smem_u32(const void* p) {
    uint32_t a;
    asm("{ .reg .u64 t; cvta.to.shared.u64 t, %1; cvt.u32.u64 %0, t; }" : "=r"(a) : "l"(p));
    return a;
}
__device__ __forceinline__ float tanh_fast(float x) {
    float y;
    asm("tanh.approx.f32 %0, %1;" : "=f"(y) : "f"(x));
    return y;
}
__device__ __forceinline__ void ldsm_x4(uint32_t& r0, uint32_t& r1, uint32_t& r2, uint32_t& r3,
                                        uint32_t addr) {
    asm volatile("ldmatrix.sync.aligned.m8n8.x4.shared.b16 {%0,%1,%2,%3}, [%4];"
        : "=r"(r0), "=r"(r1), "=r"(r2), "=r"(r3) : "r"(addr));
}
__device__ __forceinline__ void mma16816_v(float& c0, float& c1, float& c2, float& c3,
                                           uint32_t a0, uint32_t a1, uint32_t a2, uint32_t a3,
                                           uint32_t b0, uint32_t b1) {
    asm volatile(
        "mma.sync.aligned.m16n8k16.row.col.f32.f16.f16.f32 "
        "{%0,%1,%2,%3},{%4,%5,%6,%7},{%8,%9},{%0,%1,%2,%3};"
        : "+f"(c0), "+f"(c1), "+f"(c2), "+f"(c3)
        : "r"(a0), "r"(a1), "r"(a2), "r"(a3), "r"(b0), "r"(b1));
}

// One phase, fully warp-local, both nets interleaved in layer-1.
__device__ __forceinline__ void run_phase(
    int nb, float S, float V, float tcol,
    char* ab, uint32_t smb, int warp, int lane, int rl, int dup,
    float& fA, float& fB)
{
    const float4* w04 = (const float4*)(ab + OFF_W04);
    const float*  cbs = (const float*)(ab + OFF_CB);
    const float2* bw  = (const float2*)(ab + OFF_BW);
    const float*  b2s = (const float*)(ab + OFF_B2);

    const int g   = lane >> 2;
    const int tig = lane & 3;
    const int jbase = dup * 32;
    const int rsw = rl & 7;

    __syncwarp();   // WAR: prior phase's ldmatrix reads of A done before overwrite

    // ---- layer 0: units [jbase, jbase+32), XOR-swizzled 16B-unit stores ----
    {
        char* Abase = ab + OFF_A + warp * A_WARP_B + rl * A_PITCH_B;
        #pragma unroll
        for (int nl = 0; nl < 2; ++nl) {
            const int net = nb + nl;
            const float4* wp = w04 + net * 64 + jbase;
            const float*  cp = cbs + net * 64 + jbase;
            char* An = Abase + nl * A_NET_B;
            #pragma unroll
            for (int jj = 0; jj < 32; jj += 4) {
                float4 w0 = wp[jj], w1 = wp[jj + 1], w2 = wp[jj + 2], w3 = wp[jj + 3];
                float p0 = fmaf(w0.x, S, fmaf(w0.y, V, fmaf(w0.w, tcol, cp[jj])));
                float p1 = fmaf(w1.x, S, fmaf(w1.y, V, fmaf(w1.w, tcol, cp[jj + 1])));
                float p2 = fmaf(w2.x, S, fmaf(w2.y, V, fmaf(w2.w, tcol, cp[jj + 2])));
                float p3 = fmaf(w3.x, S, fmaf(w3.y, V, fmaf(w3.w, tcol, cp[jj + 3])));
                __half2 ha = __floats2half2_rn(tanh_fast(p0), tanh_fast(p1));
                __half2 hb = __floats2half2_rn(tanh_fast(p2), tanh_fast(p3));
                uint2 pk;
                pk.x = *(const uint32_t*)&ha;
                pk.y = *(const uint32_t*)&hb;
                const int unit = (dup * 4 + (jj >> 3)) ^ rsw;
                *(uint2*)(An + unit * 16 + ((jj >> 2) & 1) * 8) = pk;
            }
        }
    }
    __syncwarp();

    // ---- layer 1 + epilogue, both nets interleaved ----
    const int arow = (lane & 7) + ((lane >> 3) & 1) * 8;
    const int akh  = (lane >> 4) & 1;
    const int asw  = arow & 7;
    const uint32_t a_lane = smb + OFF_A + warp * A_WARP_B + arow * A_PITCH_B;
    const uint32_t b_lane = smb + OFF_W1T + (lane & 7) * B_ROW_B + (lane >> 3) * 16;

    uint32_t afr[2][4][4];
    #pragma unroll
    for (int nl = 0; nl < 2; ++nl) {
        const uint32_t abase = a_lane + nl * A_NET_B;
        #pragma unroll
        for (int kt = 0; kt < 4; ++kt) {
            const int unit = (kt * 2 + akh) ^ asw;
            ldsm_x4(afr[nl][kt][0], afr[nl][kt][1], afr[nl][kt][2], afr[nl][kt][3],
                    abase + unit * 16);
        }
    }

    float pr[2][2] = {{0.f, 0.f}, {0.f, 0.f}};
    const uint32_t bb0 = b_lane + (nb)     * B_NET_B;
    const uint32_t bb1 = b_lane + (nb + 1) * B_NET_B;

    #pragma unroll
    for (int j = 0; j < 8; ++j) {
        const uint32_t jofs = (uint32_t)(j * (8 * B_ROW_B));
        uint32_t x0, x1, x2, x3, x4, x5, x6, x7;   // net0 B frags
        uint32_t y0, y1, y2, y3, y4, y5, y6, y7;   // net1 B frags
        ldsm_x4(x0, x1, x2, x3, bb0 + jofs);
        ldsm_x4(x4, x5, x6, x7, bb0 + jofs + 64);
        ldsm_x4(y0, y1, y2, y3, bb1 + jofs);
        ldsm_x4(y4, y5, y6, y7, bb1 + jofs + 64);

        float cA0[4] = {0.f,0.f,0.f,0.f}, cB0[4] = {0.f,0.f,0.f,0.f};
        float cA1[4] = {0.f,0.f,0.f,0.f}, cB1[4] = {0.f,0.f,0.f,0.f};
        // 4 independent 2-deep chains
        mma16816_v(cA0[0], cA0[1], cA0[2], cA0[3],
                   afr[0][0][0], afr[0][0][1], afr[0][0][2], afr[0][0][3], x0, x1);
        mma16816_v(cB0[0], cB0[1], cB0[2], cB0[3],
                   afr[0][2][0], afr[0][2][1], afr[0][2][2], afr[0][2][3], x4, x5);
        mma16816_v(cA1[0], cA1[1], cA1[2], cA1[3],
                   afr[1][0][0], afr[1][0][1], afr[1][0][2], afr[1][0][3], y0, y1);
        mma16816_v(cB1[0], cB1[1], cB1[2], cB1[3],
                   afr[1][2][0], afr[1][2][1], afr[1][2][2], afr[1][2][3], y4, y5);
        mma16816_v(cA0[0], cA0[1], cA0[2], cA0[3],
                   afr[0][1][0], afr[0][1][1], afr[0][1][2], afr[0][1][3], x2, x3);
        mma16816_v(cB0[0], cB0[1], cB0[2], cB0[3],
                   afr[0][3][0], afr[0][3][1], afr[0][3][2], afr[0][3][3], x6, x7);
        mma16816_v(cA1[0], cA1[1], cA1[2], cA1[3],
                   afr[1][1][0], afr[1][1][1], afr[1][1][2], afr[1][1][3], y2, y3);
        mma16816_v(cB1[0], cB1[1], cB1[2], cB1[3],
                   afr[1][3][0], afr[1][3][1], afr[1][3][2], afr[1][3][3], y6, y7);

        const int n0 = j * 8 + tig * 2;
        #pragma unroll
        for (int nl = 0; nl < 2; ++nl) {
            const int net = nb + nl;
            float2 bw0 = bw[net * 64 + n0];
            float2 bw1 = bw[net * 64 + n0 + 1];
            const float* cA = nl ? cA1 : cA0;
            const float* cB = nl ? cB1 : cB0;
            float h00 = tanh_fast((cA[0] + cB[0]) + bw0.x);
            float h01 = tanh_fast((cA[1] + cB[1]) + bw1.x);
            float h10 = tanh_fast((cA[2] + cB[2]) + bw0.x);
            float h11 = tanh_fast((cA[3] + cB[3]) + bw1.x);
            pr[nl][0] = fmaf(h00, bw0.y, fmaf(h01, bw1.y, pr[nl][0]));
            pr[nl][1] = fmaf(h10, bw0.y, fmaf(h11, bw1.y, pr[nl][1]));
        }
    }

    // reduce within quad (leaves full sum in all 4 lanes of each quad)
    #pragma unroll
    for (int nl = 0; nl < 2; ++nl) {
        pr[nl][0] += __shfl_xor_sync(0xFFFFFFFFu, pr[nl][0], 1);
        pr[nl][0] += __shfl_xor_sync(0xFFFFFFFFu, pr[nl][0], 2);
        pr[nl][1] += __shfl_xor_sync(0xFFFFFFFFu, pr[nl][1], 1);
        pr[nl][1] += __shfl_xor_sync(0xFFFFFFFFu, pr[nl][1], 2);
    }
    // shuffle-based feedback: row r's value lives in quad (r&7), pr[.][r>>3]
    const int src = ((rl & 7) << 2) + tig;
    const float bbv0 = b2s[nb], bbv1 = b2s[nb + 1];
    float v00 = __shfl_sync(0xFFFFFFFFu, pr[0][0] + bbv0, src);
    float v01 = __shfl_sync(0xFFFFFFFFu, pr[0][1] + bbv0, src);
    float v10 = __shfl_sync(0xFFFFFFFFu, pr[1][0] + bbv1, src);
    float v11 = __shfl_sync(0xFFFFFFFFu, pr[1][1] + bbv1, src);
    fA = (rl < 8) ? v00 : v01;
    fB = (rl < 8) ? v10 : v11;
}

__global__ void __launch_bounds__(256, 2)
nsde_main_kernel(const float* __restrict__ S0g, const float* __restrict__ Kg,
                 const float* __restrict__ Tg,  const float* __restrict__ rfg,
                 const float* __restrict__ Z1g, const float* __restrict__ Z2g,
                 const float* __restrict__ W0g, const float* __restrict__ b0g,
                 const float* __restrict__ W1g, const float* __restrict__ b1g,
                 const float* __restrict__ W2g, const float* __restrict__ b2g)
{
    extern __shared__ char ab[];
    const uint32_t smb = smem_u32(ab);
    const int tid  = threadIdx.x;
    const int warp = tid >> 5;
    const int lane = tid & 31;
    const int rl   = lane & 15;
    const int dup  = lane >> 4;
    const int b    = blockIdx.x & 63;
    const int pb   = blockIdx.x >> 6;

    // ---- stage weights ----
    __half* W1T = (__half*)(ab + OFF_W1T);
    for (int i = tid; i < 4 * 64 * 64; i += 256) {
        const int net = i >> 12;
        const int k   = (i >> 6) & 63;
        const int n   = i & 63;
        W1T[net * 4608 + n * 72 + k] = __float2half_rn(W1g[i]);
    }
    float4* w04 = (float4*)(ab + OFF_W04);
    float*  cbs = (float*)(ab + OFF_CB);
    float2* bw  = (float2*)(ab + OFF_BW);
    float*  b2s = (float*)(ab + OFF_B2);
    float*  red = (float*)(ab + OFF_RED);
    const float rfv = rfg[0];
    {
        const int i = tid;
        const int net = i >> 6, jj = i & 63;
        float4 v;
        v.x = W0g[net * 256 + 0 * 64 + jj];
        v.y = W0g[net * 256 + 1 * 64 + jj];
        v.z = W0g[net * 256 + 2 * 64 + jj];
        v.w = W0g[net * 256 + 3 * 64 + jj];
        w04[i] = v;
        cbs[i] = fmaf(v.z, rfv, b0g[i]);
        float2 t; t.x = b1g[i]; t.y = W2g[i];
        bw[i] = t;
    }
    if (tid < 4) b2s[tid] = b2g[tid];
    __syncthreads();

    // ---- per-row state ----
    const float S0b = S0g[b], Kb = Kg[b], Tb = Tg[b];
    const float dtv  = Tb * (1.0f / 32.0f);
    const float sqdt = sqrtf(dtv);
    const int   p    = pb * 128 + warp * 16 + rl;
    const float4* z1p = (const float4*)(Z1g + p * NSTEPS);
    const float4* z2p = (const float4*)(Z2g + p * NSTEPS);
    float S = S0b, V = 0.2f;

    for (int jo = 0; jo < 8; ++jo) {
        const float4 z1v = z1p[jo];
        const float4 z2v = z2p[jo];
        #pragma unroll
        for (int ji = 0; ji < 4; ++ji) {
            const int j = jo * 4 + ji;
            const float z1 = (ji == 0) ? z1v.x : (ji == 1) ? z1v.y : (ji == 2) ? z1v.z : z1v.w;
            const float z2 = (ji == 0) ? z2v.x : (ji == 1) ? z2v.y : (ji == 2) ? z2v.z : z2v.w;
            const float tcol = dtv * (float)j;
            float fa, fb;
            run_phase(0, S, V, tcol, ab, smb, warp, lane, rl, dup, fa, fb);
            S = S * (1.0f + fa * dtv + fb * z1);
            run_phase(2, S, V, tcol, ab, smb, warp, lane, rl, dup, fa, fb);
            V = V * (1.0f + fa * dtv + fb * sqdt * z2);
        }
    }

    // ---- payoff + reduction ----
    float pay = (S - Kb < 0.0f) ? 0.0f : S;
    pay += __shfl_xor_sync(0xFFFFFFFFu, pay, 1);
    pay += __shfl_xor_sync(0xFFFFFFFFu, pay, 2);
    pay += __shfl_xor_sync(0xFFFFFFFFu, pay, 4);
    pay += __shfl_xor_sync(0xFFFFFFFFu, pay, 8);
    if (lane == 0) red[warp] = pay;
    __syncthreads();
    if (tid == 0) {
        float s = 0.f;
        #pragma unroll
        for (int w = 0; w < 8; ++w) s += red[w];
        g_partial[blockIdx.x] = s;
    }
}

__global__ void nsde_finalize_kernel(const float* __restrict__ Tg,
                                     const float* __restrict__ rfg,
                                     float* __restrict__ out)
{
    int b = threadIdx.x;
    if (b < 64) {
        float s = (g_partial[b] + g_partial[64 + b]) + (g_partial[128 + b] + g_partial[192 + b]);
        out[b] = __expf(-rfg[0] * Tg[b]) * s * (1.0f / 512.0f);
    }
}

extern "C" void kernel_launch(void* const* d_in, const int* in_sizes, int n_in,
                              void* d_out, int out_size)
{
    const float* S0 = (const float*)d_in[0];
    const float* K  = (const float*)d_in[1];
    const float* T  = (const float*)d_in[2];
    const float* rf = (const float*)d_in[3];
    const float* Z1 = (const float*)d_in[4];
    const float* Z2 = (const float*)d_in[5];
    const float* W0 = (const float*)d_in[6];
    const float* b0 = (const float*)d_in[7];
    const float* W1 = (const float*)d_in[8];
    const float* b1 = (const float*)d_in[9];
    const float* W2 = (const float*)d_in[10];
    const float* b2 = (const float*)d_in[11];
    float* out = (float*)d_out;

    cudaFuncSetAttribute(nsde_main_kernel, cudaFuncAttributeMaxDynamicSharedMemorySize, SMEM_BYTES);
    nsde_main_kernel<<<256, 256, SMEM_BYTES>>>(S0, K, T, rf, Z1, Z2, W0, b0, W1, b1, W2, b2);
    nsde_finalize_kernel<<<1, 64>>>(T, rf, out);
}